// round 1
// baseline (speedup 1.0000x reference)
#include <cuda_runtime.h>
#include <math.h>

#define NB 8
#define NS 2048
#define ND 256
#define NE 256
static constexpr float kScale = 0.125f;  // 1/sqrt(64), per reference source

// Scratch for Q, K, V projections (allocation-free: __device__ globals)
__device__ float g_Q[NB * NS * NE];
__device__ float g_K[NB * NS * NE];
__device__ float g_V[NB * NS * NE];

// ---------------------------------------------------------------------------
// QKV projection: C_p = X(16384x256) @ W_p(256x256), p = blockIdx.z in {0,1,2}
// 64x64 block tile, 4x4 micro tile per thread, K staged 16 at a time.
// ---------------------------------------------------------------------------
__global__ __launch_bounds__(256) void qkv_kernel(const float* __restrict__ x,
                                                  const float* __restrict__ w) {
    __shared__ __align__(16) float As[64][20];  // 80B row stride (16B aligned)
    __shared__ __align__(16) float Bs[16][68];  // 272B row stride (16B aligned)

    const int p = blockIdx.z;
    const float* W = w + (size_t)p * ND * NE;
    float* out = (p == 0) ? g_Q : ((p == 1) ? g_K : g_V);
    const int row0 = blockIdx.x * 64;
    const int col0 = blockIdx.y * 64;
    const int tid = threadIdx.x;
    const int tx = tid & 15;
    const int ty = tid >> 4;

    float4 acc[4];
#pragma unroll
    for (int i = 0; i < 4; i++) acc[i] = make_float4(0.f, 0.f, 0.f, 0.f);

    for (int k0 = 0; k0 < ND; k0 += 16) {
        {   // load X tile 64x16 (one float4 per thread)
            int r = tid >> 2;
            int c = (tid & 3) << 2;
            float4 v = *(const float4*)&x[(size_t)(row0 + r) * ND + k0 + c];
            *(float4*)&As[r][c] = v;
        }
        {   // load W tile 16x64 (one float4 per thread)
            int r = tid >> 4;
            int c = (tid & 15) << 2;
            float4 v = *(const float4*)&W[(size_t)(k0 + r) * NE + col0 + c];
            *(float4*)&Bs[r][c] = v;
        }
        __syncthreads();
#pragma unroll
        for (int kk = 0; kk < 16; kk++) {
            float4 bv = *(const float4*)&Bs[kk][tx << 2];
#pragma unroll
            for (int i = 0; i < 4; i++) {
                float a = As[(ty << 2) + i][kk];
                acc[i].x += a * bv.x;
                acc[i].y += a * bv.y;
                acc[i].z += a * bv.z;
                acc[i].w += a * bv.w;
            }
        }
        __syncthreads();
    }
#pragma unroll
    for (int i = 0; i < 4; i++) {
        *(float4*)&out[(size_t)(row0 + (ty << 2) + i) * NE + col0 + (tx << 2)] = acc[i];
    }
}

// ---------------------------------------------------------------------------
// Flash-attention style: one block = 64 queries of one batch.
// Streams 32 K/V tiles (64 keys each) through shared memory; online softmax.
// Thread (ty,tx) of 16x16 grid owns query rows ty+16i (i<4), key cols tx+16j,
// and output cols (tx*4 .. tx*4+3) + 64*cc (cc<4). Row mapping lane+16k keeps
// float4 smem reads conflict-free (8-lane phases hit 8 distinct bank groups).
// ---------------------------------------------------------------------------
__global__ __launch_bounds__(256, 1) void attn_kernel(const int* __restrict__ mask,
                                                      float* __restrict__ out) {
    extern __shared__ float sm[];
    float* Qs = sm;               // [64][260]
    float* Ks = Qs + 64 * 260;    // [64][260]
    float* Vs = Ks + 64 * 260;    // [64][260]
    float* Ps = Vs + 64 * 260;    // [64][68]
    float* rs = Ps + 64 * 68;     // [64] row scale = kScale * mask

    const int b  = blockIdx.y;
    const int q0 = blockIdx.x * 64;
    const float* __restrict__ Qg = g_Q + (size_t)b * NS * NE;
    const float* __restrict__ Kg = g_K + (size_t)b * NS * NE;
    const float* __restrict__ Vg = g_V + (size_t)b * NS * NE;

    const int tid = threadIdx.x;
    const int tx = tid & 15;
    const int ty = tid >> 4;

    // Load Q tile (64x256 floats = 4096 float4, 16 per thread)
    for (int i = tid; i < 64 * 64; i += 256) {
        int r = i >> 6;
        int c = (i & 63) << 2;
        *(float4*)&Qs[r * 260 + c] = *(const float4*)&Qg[(size_t)(q0 + r) * NE + c];
    }
    if (tid < 64) rs[tid] = kScale * (float)mask[b * NS + q0 + tid];
    __syncthreads();

    int qr[4];
    float rscale[4];
#pragma unroll
    for (int i = 0; i < 4; i++) { qr[i] = ty + 16 * i; rscale[i] = rs[qr[i]]; }

    float4 O[4][4];
#pragma unroll
    for (int i = 0; i < 4; i++)
#pragma unroll
        for (int cc = 0; cc < 4; cc++) O[i][cc] = make_float4(0.f, 0.f, 0.f, 0.f);

    float m_run[4], l_run[4];
#pragma unroll
    for (int i = 0; i < 4; i++) { m_run[i] = -INFINITY; l_run[i] = 0.f; }

    for (int kt = 0; kt < NS / 64; kt++) {
        const int k0 = kt * 64;
        // Load K and V tiles (32 float4 per thread)
        for (int i = tid; i < 64 * 64; i += 256) {
            int r = i >> 6;
            int c = (i & 63) << 2;
            *(float4*)&Ks[r * 260 + c] = *(const float4*)&Kg[(size_t)(k0 + r) * NE + c];
            *(float4*)&Vs[r * 260 + c] = *(const float4*)&Vg[(size_t)(k0 + r) * NE + c];
        }
        __syncthreads();

        // Scores: s[i][j] = Q[qr[i]] . K[tx+16j]
        float s[4][4];
#pragma unroll
        for (int i = 0; i < 4; i++)
#pragma unroll
            for (int j = 0; j < 4; j++) s[i][j] = 0.f;

        for (int e = 0; e < NE; e += 4) {
            float4 qv[4], kv[4];
#pragma unroll
            for (int i = 0; i < 4; i++) qv[i] = *(const float4*)&Qs[qr[i] * 260 + e];
#pragma unroll
            for (int j = 0; j < 4; j++) kv[j] = *(const float4*)&Ks[(tx + 16 * j) * 260 + e];
#pragma unroll
            for (int i = 0; i < 4; i++)
#pragma unroll
                for (int j = 0; j < 4; j++) {
                    s[i][j] += qv[i].x * kv[j].x;
                    s[i][j] += qv[i].y * kv[j].y;
                    s[i][j] += qv[i].z * kv[j].z;
                    s[i][j] += qv[i].w * kv[j].w;
                }
        }

        // Multiplicative row mask + scale, then online softmax update
        float p[4][4];
#pragma unroll
        for (int i = 0; i < 4; i++) {
#pragma unroll
            for (int j = 0; j < 4; j++) s[i][j] *= rscale[i];

            float mt = fmaxf(fmaxf(s[i][0], s[i][1]), fmaxf(s[i][2], s[i][3]));
            mt = fmaxf(mt, __shfl_xor_sync(0xffffffffu, mt, 8));
            mt = fmaxf(mt, __shfl_xor_sync(0xffffffffu, mt, 4));
            mt = fmaxf(mt, __shfl_xor_sync(0xffffffffu, mt, 2));
            mt = fmaxf(mt, __shfl_xor_sync(0xffffffffu, mt, 1));
            float mn = fmaxf(m_run[i], mt);

            float sum = 0.f;
#pragma unroll
            for (int j = 0; j < 4; j++) {
                p[i][j] = __expf(s[i][j] - mn);
                sum += p[i][j];
            }
            sum += __shfl_xor_sync(0xffffffffu, sum, 8);
            sum += __shfl_xor_sync(0xffffffffu, sum, 4);
            sum += __shfl_xor_sync(0xffffffffu, sum, 2);
            sum += __shfl_xor_sync(0xffffffffu, sum, 1);

            float alpha = __expf(m_run[i] - mn);  // 0 on first tile (m_run=-inf)
            l_run[i] = l_run[i] * alpha + sum;
            m_run[i] = mn;
#pragma unroll
            for (int cc = 0; cc < 4; cc++) {
                O[i][cc].x *= alpha; O[i][cc].y *= alpha;
                O[i][cc].z *= alpha; O[i][cc].w *= alpha;
            }
        }

        // Stage P to shared for the PV GEMM
#pragma unroll
        for (int i = 0; i < 4; i++)
#pragma unroll
            for (int j = 0; j < 4; j++) Ps[qr[i] * 68 + tx + 16 * j] = p[i][j];
        __syncthreads();

        // O += P @ V
        for (int j = 0; j < 64; j++) {
            float pr[4];
#pragma unroll
            for (int i = 0; i < 4; i++) pr[i] = Ps[qr[i] * 68 + j];
            float4 vv[4];
#pragma unroll
            for (int cc = 0; cc < 4; cc++)
                vv[cc] = *(const float4*)&Vs[j * 260 + (tx << 2) + 64 * cc];
#pragma unroll
            for (int i = 0; i < 4; i++)
#pragma unroll
                for (int cc = 0; cc < 4; cc++) {
                    O[i][cc].x += pr[i] * vv[cc].x;
                    O[i][cc].y += pr[i] * vv[cc].y;
                    O[i][cc].z += pr[i] * vv[cc].z;
                    O[i][cc].w += pr[i] * vv[cc].w;
                }
        }
        __syncthreads();
    }

    // Epilogue: normalize and store
#pragma unroll
    for (int i = 0; i < 4; i++) {
        float inv = 1.0f / l_run[i];
#pragma unroll
        for (int cc = 0; cc < 4; cc++) {
            float4 o = O[i][cc];
            o.x *= inv; o.y *= inv; o.z *= inv; o.w *= inv;
            *(float4*)&out[(size_t)(b * NS + q0 + qr[i]) * NE + (tx << 2) + 64 * cc] = o;
        }
    }
}

// ---------------------------------------------------------------------------
extern "C" void kernel_launch(void* const* d_in, const int* in_sizes, int n_in,
                              void* d_out, int out_size) {
    (void)in_sizes; (void)n_in; (void)out_size;
    const float* x    = (const float*)d_in[0];  // [8, 2048, 256] f32
    const float* w    = (const float*)d_in[1];  // [3, 256, 256]  f32
    const int*   mask = (const int*)d_in[2];    // [8, 2048]      i32
    float* out = (float*)d_out;                 // [8, 2048, 256] f32

    dim3 g1((NB * NS) / 64, NE / 64, 3);
    qkv_kernel<<<g1, 256>>>(x, w);

    const size_t smem = (size_t)(3 * 64 * 260 + 64 * 68 + 64) * sizeof(float);  // 217,344 B
    cudaFuncSetAttribute(attn_kernel, cudaFuncAttributeMaxDynamicSharedMemorySize,
                         (int)smem);
    dim3 g2(NS / 64, NB);
    attn_kernel<<<g2, 256, smem>>>(mask, out);
}

// round 2
// speedup vs baseline: 1.2084x; 1.2084x over previous
#include <cuda_runtime.h>
#include <math.h>

#define NB 8
#define NS 2048
#define ND 256
#define NE 256
static constexpr float kScale = 0.125f;  // 1/sqrt(64), per reference source

typedef unsigned long long u64;

// ---- packed f32x2 helpers (SASS FFMA2/FMUL2 — ptxas never emits these) ----
__device__ __forceinline__ u64 pack2(float x, float y) {
    u64 r;
    asm("mov.b64 %0, {%1, %2};" : "=l"(r) : "r"(__float_as_uint(x)), "r"(__float_as_uint(y)));
    return r;
}
__device__ __forceinline__ void unpack2(u64 v, float& x, float& y) {
    unsigned lo, hi;
    asm("mov.b64 {%0, %1}, %2;" : "=r"(lo), "=r"(hi) : "l"(v));
    x = __uint_as_float(lo);
    y = __uint_as_float(hi);
}
__device__ __forceinline__ void ffma2(u64& d, u64 a, u64 b) {
    asm("fma.rn.f32x2 %0, %1, %2, %0;" : "+l"(d) : "l"(a), "l"(b));
}
__device__ __forceinline__ void fmul2(u64& d, u64 a) {
    asm("mul.rn.f32x2 %0, %0, %1;" : "+l"(d) : "l"(a));
}

// ---- cp.async 16B ----
__device__ __forceinline__ void cp16(void* smem_dst, const void* gmem_src) {
    unsigned dst = (unsigned)__cvta_generic_to_shared(smem_dst);
    asm volatile("cp.async.cg.shared.global [%0], [%1], 16;" :: "r"(dst), "l"(gmem_src));
}
__device__ __forceinline__ void cp_wait_all() {
    asm volatile("cp.async.commit_group;\n\tcp.async.wait_group 0;" ::: "memory");
}

// Scratch for Q, K, V projections (allocation-free: __device__ globals)
__device__ float g_Q[NB * NS * NE];
__device__ float g_K[NB * NS * NE];
__device__ float g_V[NB * NS * NE];

// ---------------------------------------------------------------------------
// QKV projection: C_p = X(16384x256) @ W_p(256x256), p = blockIdx.z in {0,1,2}
// 64x64 block tile, 4x4 micro tile per thread, K staged 16 at a time. FFMA2.
// ---------------------------------------------------------------------------
__global__ __launch_bounds__(256) void qkv_kernel(const float* __restrict__ x,
                                                  const float* __restrict__ w) {
    __shared__ __align__(16) float As[64][20];
    __shared__ __align__(16) float Bs[16][68];

    const int p = blockIdx.z;
    const float* W = w + (size_t)p * ND * NE;
    float* out = (p == 0) ? g_Q : ((p == 1) ? g_K : g_V);
    const int row0 = blockIdx.x * 64;
    const int col0 = blockIdx.y * 64;
    const int tid = threadIdx.x;
    const int tx = tid & 15;
    const int ty = tid >> 4;

    ulonglong2 acc[4];
#pragma unroll
    for (int i = 0; i < 4; i++) { acc[i].x = 0ull; acc[i].y = 0ull; }

    for (int k0 = 0; k0 < ND; k0 += 16) {
        {
            int r = tid >> 2;
            int c = (tid & 3) << 2;
            cp16(&As[r][c], &x[(size_t)(row0 + r) * ND + k0 + c]);
        }
        {
            int r = tid >> 4;
            int c = (tid & 15) << 2;
            cp16(&Bs[r][c], &W[(size_t)(k0 + r) * NE + col0 + c]);
        }
        cp_wait_all();
        __syncthreads();
#pragma unroll
        for (int kk = 0; kk < 16; kk++) {
            ulonglong2 bv = *(const ulonglong2*)&Bs[kk][tx << 2];
#pragma unroll
            for (int i = 0; i < 4; i++) {
                float a = As[(ty << 2) + i][kk];
                u64 ap = pack2(a, a);
                ffma2(acc[i].x, ap, bv.x);
                ffma2(acc[i].y, ap, bv.y);
            }
        }
        __syncthreads();
    }
#pragma unroll
    for (int i = 0; i < 4; i++) {
        *(ulonglong2*)&out[(size_t)(row0 + (ty << 2) + i) * NE + col0 + (tx << 2)] = acc[i];
    }
}

// ---------------------------------------------------------------------------
// Flash-attention style: one block = 64 queries of one batch; 32 x 64-key tiles.
// Thread (ty,tx) of 16x16: query rows ty+16i, key cols tx+16j, out cols
// tx*4+64*cc. All heavy FMAs are packed f32x2 (FFMA2).
// ---------------------------------------------------------------------------
__global__ __launch_bounds__(256, 1) void attn_kernel(const int* __restrict__ mask,
                                                      float* __restrict__ out) {
    extern __shared__ float sm[];
    float* Qs = sm;               // [64][260]
    float* Ks = Qs + 64 * 260;    // [64][260]
    float* Vs = Ks + 64 * 260;    // [64][260]
    float* Ps = Vs + 64 * 260;    // [64][68]
    float* rs = Ps + 64 * 68;     // [64]

    const int b  = blockIdx.y;
    const int q0 = blockIdx.x * 64;
    const float* __restrict__ Qg = g_Q + (size_t)b * NS * NE;
    const float* __restrict__ Kg = g_K + (size_t)b * NS * NE;
    const float* __restrict__ Vg = g_V + (size_t)b * NS * NE;

    const int tid = threadIdx.x;
    const int tx = tid & 15;
    const int ty = tid >> 4;

    // Load Q tile via cp.async (16 x 16B per thread)
    for (int i = tid; i < 64 * 64; i += 256) {
        int r = i >> 6;
        int c = (i & 63) << 2;
        cp16(&Qs[r * 260 + c], &Qg[(size_t)(q0 + r) * NE + c]);
    }
    if (tid < 64) rs[tid] = kScale * (float)mask[b * NS + q0 + tid];
    cp_wait_all();
    __syncthreads();

    int qr[4];
    float rscale[4];
#pragma unroll
    for (int i = 0; i < 4; i++) { qr[i] = ty + 16 * i; rscale[i] = rs[qr[i]]; }

    ulonglong2 O2[4][4];  // 4 rows x 16 cols as 8 f32x2 lanes per row-group
#pragma unroll
    for (int i = 0; i < 4; i++)
#pragma unroll
        for (int cc = 0; cc < 4; cc++) { O2[i][cc].x = 0ull; O2[i][cc].y = 0ull; }

    float m_run[4], l_run[4];
#pragma unroll
    for (int i = 0; i < 4; i++) { m_run[i] = -INFINITY; l_run[i] = 0.f; }

    for (int kt = 0; kt < NS / 64; kt++) {
        const int k0 = kt * 64;
        for (int i = tid; i < 64 * 64; i += 256) {
            int r = i >> 6;
            int c = (i & 63) << 2;
            cp16(&Ks[r * 260 + c], &Kg[(size_t)(k0 + r) * NE + c]);
            cp16(&Vs[r * 260 + c], &Vg[(size_t)(k0 + r) * NE + c]);
        }
        cp_wait_all();
        __syncthreads();

        // Scores via FFMA2: accumulate (even-e, odd-e) lanes, reduce at end.
        u64 s2[4][4];
#pragma unroll
        for (int i = 0; i < 4; i++)
#pragma unroll
            for (int j = 0; j < 4; j++) s2[i][j] = 0ull;

        for (int e = 0; e < NE; e += 4) {
            ulonglong2 qv[4], kv[4];
#pragma unroll
            for (int i = 0; i < 4; i++) qv[i] = *(const ulonglong2*)&Qs[qr[i] * 260 + e];
#pragma unroll
            for (int j = 0; j < 4; j++) kv[j] = *(const ulonglong2*)&Ks[(tx + 16 * j) * 260 + e];
#pragma unroll
            for (int i = 0; i < 4; i++)
#pragma unroll
                for (int j = 0; j < 4; j++) {
                    ffma2(s2[i][j], qv[i].x, kv[j].x);
                    ffma2(s2[i][j], qv[i].y, kv[j].y);
                }
        }

        // Multiplicative row mask + scale, online softmax update
        float p[4][4];
#pragma unroll
        for (int i = 0; i < 4; i++) {
            float s[4];
#pragma unroll
            for (int j = 0; j < 4; j++) {
                float lo, hi;
                unpack2(s2[i][j], lo, hi);
                s[j] = (lo + hi) * rscale[i];
            }

            float mt = fmaxf(fmaxf(s[0], s[1]), fmaxf(s[2], s[3]));
            mt = fmaxf(mt, __shfl_xor_sync(0xffffffffu, mt, 8));
            mt = fmaxf(mt, __shfl_xor_sync(0xffffffffu, mt, 4));
            mt = fmaxf(mt, __shfl_xor_sync(0xffffffffu, mt, 2));
            mt = fmaxf(mt, __shfl_xor_sync(0xffffffffu, mt, 1));
            float mn = fmaxf(m_run[i], mt);

            float sum = 0.f;
#pragma unroll
            for (int j = 0; j < 4; j++) {
                p[i][j] = __expf(s[j] - mn);
                sum += p[i][j];
            }
            sum += __shfl_xor_sync(0xffffffffu, sum, 8);
            sum += __shfl_xor_sync(0xffffffffu, sum, 4);
            sum += __shfl_xor_sync(0xffffffffu, sum, 2);
            sum += __shfl_xor_sync(0xffffffffu, sum, 1);

            float alpha = __expf(m_run[i] - mn);  // 0 on first tile
            l_run[i] = l_run[i] * alpha + sum;
            m_run[i] = mn;
            u64 a2 = pack2(alpha, alpha);
#pragma unroll
            for (int cc = 0; cc < 4; cc++) {
                fmul2(O2[i][cc].x, a2);
                fmul2(O2[i][cc].y, a2);
            }
        }

        // Stage P via smem; producer == consumer half-warp, so __syncwarp only.
#pragma unroll
        for (int i = 0; i < 4; i++)
#pragma unroll
            for (int j = 0; j < 4; j++) Ps[qr[i] * 68 + tx + 16 * j] = p[i][j];
        __syncwarp();

        // O += P @ V (FFMA2 over column pairs)
        for (int j = 0; j < 64; j++) {
            u64 pp[4];
#pragma unroll
            for (int i = 0; i < 4; i++) {
                float pr = Ps[qr[i] * 68 + j];
                pp[i] = pack2(pr, pr);
            }
            ulonglong2 vv[4];
#pragma unroll
            for (int cc = 0; cc < 4; cc++)
                vv[cc] = *(const ulonglong2*)&Vs[j * 260 + (tx << 2) + 64 * cc];
#pragma unroll
            for (int i = 0; i < 4; i++)
#pragma unroll
                for (int cc = 0; cc < 4; cc++) {
                    ffma2(O2[i][cc].x, pp[i], vv[cc].x);
                    ffma2(O2[i][cc].y, pp[i], vv[cc].y);
                }
        }
        __syncthreads();
    }

    // Epilogue: normalize (packed) and store 16B per (i,cc)
#pragma unroll
    for (int i = 0; i < 4; i++) {
        float inv = 1.0f / l_run[i];
        u64 inv2 = pack2(inv, inv);
#pragma unroll
        for (int cc = 0; cc < 4; cc++) {
            fmul2(O2[i][cc].x, inv2);
            fmul2(O2[i][cc].y, inv2);
            *(ulonglong2*)&out[(size_t)(b * NS + q0 + qr[i]) * NE + (tx << 2) + 64 * cc] =
                O2[i][cc];
        }
    }
}

// ---------------------------------------------------------------------------
extern "C" void kernel_launch(void* const* d_in, const int* in_sizes, int n_in,
                              void* d_out, int out_size) {
    (void)in_sizes; (void)n_in; (void)out_size;
    const float* x    = (const float*)d_in[0];  // [8, 2048, 256] f32
    const float* w    = (const float*)d_in[1];  // [3, 256, 256]  f32
    const int*   mask = (const int*)d_in[2];    // [8, 2048]      i32
    float* out = (float*)d_out;                 // [8, 2048, 256] f32

    dim3 g1((NB * NS) / 64, NE / 64, 3);
    qkv_kernel<<<g1, 256>>>(x, w);

    const size_t smem = (size_t)(3 * 64 * 260 + 64 * 68 + 64) * sizeof(float);  // 217,344 B
    cudaFuncSetAttribute(attn_kernel, cudaFuncAttributeMaxDynamicSharedMemorySize,
                         (int)smem);
    dim3 g2(NS / 64, NB);
    attn_kernel<<<g2, 256, smem>>>(mask, out);
}